// round 10
// baseline (speedup 1.0000x reference)
#include <cuda_runtime.h>
#include <cuda_bf16.h>
#include <mma.h>
#include <cstdint>

using namespace nvcuda;

#define FULLMASK 0xffffffffu

// ---------------- problem dims ----------------
#define DMODEL 2048
#define DINNER 2048
#define DXB    512
#define DSTATE 32
#define DTRANK 128
#define DFF    5632
#define NTOK   2048      // BATCH * SEQ
#define SEQLEN 1024
#define PROJ   5248      // 2*DINNER + 2*DXB + DTRANK

// column offsets inside zxbcdt
#define OFF_Z  0
#define OFF_X  2048
#define OFF_B  2560
#define OFF_C  3072
#define OFF_DT 5120

// ---------------- scratch (device globals; no allocation allowed) ----------------
__device__ float g_xn1[(size_t)NTOK * DMODEL];
__device__ float g_zx [(size_t)NTOK * PROJ];
__device__ float g_dt [(size_t)NTOK * DINNER];
__device__ float g_ypart[(size_t)128 * 1024 * 128];   // [seq][t][warp*32+p]
__device__ float g_yg [(size_t)NTOK * DINNER];
__device__ float g_h  [(size_t)NTOK * DMODEL];
__device__ float g_xn2[(size_t)NTOK * DMODEL];
__device__ float g_gate[(size_t)NTOK * DFF];
__device__ float g_ff [(size_t)NTOK * DFF];
__device__ float g_wtmp[(size_t)DFF * DMODEL];        // rounded-weight staging (largest weight)

// ---------------- helpers ----------------
__device__ __forceinline__ float softplusf(float x) {
    return (x > 15.f) ? x : log1pf(__expf(x));
}
__device__ __forceinline__ float siluf(float x) {
    return x / (1.f + __expf(-x));
}
__device__ __forceinline__ float round_tf32(float x) {
    unsigned r;
    asm("cvt.rna.tf32.f32 %0, %1;" : "=r"(r) : "f"(x));
    return __uint_as_float(r);
}

__device__ __forceinline__ void cp_async16(void* smem_ptr, const void* gmem_ptr) {
    unsigned saddr = (unsigned)__cvta_generic_to_shared(smem_ptr);
    asm volatile("cp.async.cg.shared.global [%0], [%1], 16;\n" :: "r"(saddr), "l"(gmem_ptr));
}
#define CP_COMMIT()  asm volatile("cp.async.commit_group;\n" ::: "memory")
#define CP_WAIT0()   asm volatile("cp.async.wait_group 0;\n" ::: "memory")
#define CP_WAIT1()   asm volatile("cp.async.wait_group 1;\n" ::: "memory")

// ---------------- weight rounding: fp32 -> tf32(RN) staging ----------------
__global__ void roundw_kernel(const float4* __restrict__ in, float4* __restrict__ out, int n4)
{
    int i = blockIdx.x * 256 + threadIdx.x;
    if (i < n4) {
        float4 v = in[i];
        v.x = round_tf32(v.x); v.y = round_tf32(v.y);
        v.z = round_tf32(v.z); v.w = round_tf32(v.w);
        out[i] = v;
    }
}

// ---------------- RMSNorm (tf32-RN rounded output: feeds GEMM A) ----------------
__global__ void rmsnorm_kernel(const float* __restrict__ x,
                               const float* __restrict__ w,
                               float* __restrict__ out)
{
    int t = blockIdx.x;
    const float* xr = x + (size_t)t * DMODEL;
    float s = 0.f;
    const float4* x4 = (const float4*)xr;
    #pragma unroll
    for (int i = threadIdx.x; i < DMODEL / 4; i += 256) {
        float4 v = x4[i];
        s += v.x * v.x + v.y * v.y + v.z * v.z + v.w * v.w;
    }
    #pragma unroll
    for (int o = 16; o; o >>= 1) s += __shfl_xor_sync(FULLMASK, s, o);
    __shared__ float red[8];
    if ((threadIdx.x & 31) == 0) red[threadIdx.x >> 5] = s;
    __syncthreads();
    if (threadIdx.x == 0) {
        float r = 0.f;
        #pragma unroll
        for (int i = 0; i < 8; i++) r += red[i];
        red[0] = rsqrtf(r / (float)DMODEL + 1e-5f);
    }
    __syncthreads();
    float inv = red[0];
    float* orow = out + (size_t)t * DMODEL;
    for (int i = threadIdx.x; i < DMODEL; i += 256)
        orow[i] = round_tf32(xr[i] * inv * w[i]);
}

// ---------------- GEMM v5: C[M,N] = A[M,K] * B[N,K]^T  (wmma TF32, no in-kernel cvt) ----------------
// Operands MUST already be tf32-representable (RN-pre-rounded); HMMA truncation is then exact.
// 128x128 block tile, BK=32, 256 threads (8 warps, 2x4), 2-stage cp.async pipeline.
// MODE 0: round_tf32(acc)              (in_proj -> zx, feeds dt GEMM)
// MODE 1: softplus(acc + bias[n])      (dt)
// MODE 2: acc + extra[m,n]             (out_proj, down: residual adds, full precision)
// MODE 3: plain                        (gate)
// MODE 4: round_tf32(acc*silu(extra))  (up fused, feeds down GEMM)
#define SASTRIDE 36
#define STAGEF   (128 * SASTRIDE)     // floats per stage per matrix

template <int MODE>
__global__ __launch_bounds__(256)
void gemm128(const float* __restrict__ A, int lda,
             const float* __restrict__ B, int ldb,
             float* __restrict__ C, int ldc,
             const float* __restrict__ extra,
             int K)
{
    extern __shared__ float smem[];
    float* sA[2] = { smem,             smem + STAGEF };
    float* sB[2] = { smem + 2*STAGEF,  smem + 3*STAGEF };

    const int bm = blockIdx.y * 128;
    const int bn = blockIdx.x * 128;
    const int tid = threadIdx.x;
    const int wid = tid >> 5;
    const int wm = (wid >> 2) * 64;   // 0 or 64
    const int wn = (wid & 3) * 32;    // 0,32,64,96

    wmma::fragment<wmma::accumulator, 16, 16, 8, float> acc[4][2];
    #pragma unroll
    for (int i = 0; i < 4; i++)
        #pragma unroll
        for (int j = 0; j < 2; j++)
            wmma::fill_fragment(acc[i][j], 0.f);

    const int kTiles = K >> 5;

    // loader: 128x32 tile = 1024 16B-chunks per matrix, 4 per thread per matrix
    auto load_stage = [&](int st, int k0) {
        #pragma unroll
        for (int i = 0; i < 4; i++) {
            int chunk = tid + i * 256;
            int r = chunk >> 3, c = (chunk & 7) << 2;
            cp_async16(sA[st] + r * SASTRIDE + c,
                       A + (size_t)(bm + r) * lda + k0 + c);
            cp_async16(sB[st] + r * SASTRIDE + c,
                       B + (size_t)(bn + r) * ldb + k0 + c);
        }
    };

    load_stage(0, 0);
    CP_COMMIT();

    for (int kt = 0; kt < kTiles; kt++) {
        int st = kt & 1;
        if (kt + 1 < kTiles) {
            load_stage(st ^ 1, (kt + 1) << 5);
            CP_COMMIT();
            CP_WAIT1();
        } else {
            CP_WAIT0();
        }
        __syncthreads();

        #pragma unroll
        for (int kk = 0; kk < 32; kk += 8) {
            wmma::fragment<wmma::matrix_a, 16, 16, 8, wmma::precision::tf32, wmma::row_major> af[4];
            wmma::fragment<wmma::matrix_b, 16, 16, 8, wmma::precision::tf32, wmma::col_major> bf[2];
            #pragma unroll
            for (int i = 0; i < 4; i++)
                wmma::load_matrix_sync(af[i], sA[st] + (wm + i * 16) * SASTRIDE + kk, SASTRIDE);
            #pragma unroll
            for (int j = 0; j < 2; j++)
                wmma::load_matrix_sync(bf[j], sB[st] + (wn + j * 16) * SASTRIDE + kk, SASTRIDE);
            #pragma unroll
            for (int i = 0; i < 4; i++)
                #pragma unroll
                for (int j = 0; j < 2; j++)
                    wmma::mma_sync(acc[i][j], af[i], bf[j], acc[i][j]);
        }
        __syncthreads();
    }

    // stage the 128x128 C tile through smem (reuse buffer), then epilogue
    #pragma unroll
    for (int i = 0; i < 4; i++)
        #pragma unroll
        for (int j = 0; j < 2; j++)
            wmma::store_matrix_sync(smem + (wm + i * 16) * 128 + wn + j * 16,
                                    acc[i][j], 128, wmma::mem_row_major);
    __syncthreads();

    #pragma unroll 4
    for (int i = tid; i < 128 * 128; i += 256) {
        int r = i >> 7, c = i & 127;
        float v = smem[i];
        int gm = bm + r, gn = bn + c;
        if (MODE == 0) v = round_tf32(v);
        if (MODE == 1) v = softplusf(v + extra[gn]);
        if (MODE == 2) v += extra[(size_t)gm * ldc + gn];
        if (MODE == 4) v = round_tf32(v * siluf(extra[(size_t)gm * ldc + gn]));
        C[(size_t)gm * ldc + gn] = v;
    }
}

// ---------------- selective scan ----------------
// grid = 128 (b*g), block = 128 (4 warps). lane = p, warp owns 8 n-columns.
#define PF 8
__global__ __launch_bounds__(128)
void scan_kernel(const float* __restrict__ zx,
                 const float* __restrict__ dtbuf,
                 const float* __restrict__ A_log,
                 float* __restrict__ ypart)
{
    int seq = blockIdx.x;          // 0..127
    int b = seq >> 6;
    int g = seq & 63;
    int w = threadIdx.x >> 5;      // 0..3
    int p = threadIdx.x & 31;      // lane
    int gkv = g >> 2;
    int nbase = w * 8;

    float An[8];
    #pragma unroll
    for (int j = 0; j < 8; j++)
        An[j] = -__expf(A_log[(size_t)(g * 32 + p) * DSTATE + nbase + j]);

    float h[8];
    #pragma unroll
    for (int j = 0; j < 8; j++) h[j] = 0.f;

    const float* dt_base = dtbuf + (size_t)b * SEQLEN * DINNER + g * 32 + p;
    const float* x_base  = zx + (size_t)b * SEQLEN * PROJ + OFF_X + gkv * 32 + p;
    const float* B_base  = zx + (size_t)b * SEQLEN * PROJ + OFF_B + gkv * 32 + p;  // lane = n
    const float* C_base  = zx + (size_t)b * SEQLEN * PROJ + OFF_C + g * 32 + p;    // lane = n
    float* yp = ypart + ((size_t)seq * SEQLEN) * 128 + w * 32 + p;

    float pdt[PF], px[PF], pB[PF], pC[PF];
    #pragma unroll
    for (int i = 0; i < PF; i++) {
        pdt[i] = __ldg(dt_base + (size_t)i * DINNER);
        px[i]  = __ldg(x_base  + (size_t)i * PROJ);
        pB[i]  = __ldg(B_base  + (size_t)i * PROJ);
        pC[i]  = __ldg(C_base  + (size_t)i * PROJ);
    }

    #pragma unroll 8
    for (int t = 0; t < SEQLEN; t++) {
        int slot = t & (PF - 1);
        float dtv = pdt[slot], xv = px[slot], Ball = pB[slot], Call = pC[slot];
        int tn = t + PF;
        if (tn < SEQLEN) {
            pdt[slot] = __ldg(dt_base + (size_t)tn * DINNER);
            px[slot]  = __ldg(x_base  + (size_t)tn * PROJ);
            pB[slot]  = __ldg(B_base  + (size_t)tn * PROJ);
            pC[slot]  = __ldg(C_base  + (size_t)tn * PROJ);
        }
        float dtx = dtv * xv;
        float acc = 0.f;
        #pragma unroll
        for (int j = 0; j < 8; j++) {
            float Bv = __shfl_sync(FULLMASK, Ball, nbase + j);
            float Cv = __shfl_sync(FULLMASK, Call, nbase + j);
            float dA = __expf(dtv * An[j]);
            h[j] = dA * h[j] + dtx * Bv;
            acc += h[j] * Cv;
        }
        yp[(size_t)t * 128] = acc;
    }
}

// ---------------- combine partial y + skip D + silu(z) gate (tf32-rounded: feeds out_proj) ----------------
__global__ void combine_kernel(const float* __restrict__ ypart,
                               const float* __restrict__ zx,
                               const float* __restrict__ Dp,
                               float* __restrict__ out)
{
    int idx = blockIdx.x * 256 + threadIdx.x;      // 0 .. NTOK*DINNER
    int tok = idx >> 11;
    int i   = idx & 2047;
    int b = tok >> 10, t = tok & 1023;
    int g = i >> 5, p = i & 31;
    int seq = b * 64 + g;
    int gkv = g >> 2;

    const float* yp = ypart + ((size_t)seq * SEQLEN + t) * 128 + p;
    float y = yp[0] + yp[32] + yp[64] + yp[96];

    float xv = zx[(size_t)tok * PROJ + OFF_X + gkv * 32 + p];
    float zv = zx[(size_t)tok * PROJ + OFF_Z + i];
    y += xv * Dp[i];
    float sig = 1.f / (1.f + __expf(-zv));
    out[(size_t)tok * DINNER + i] = round_tf32(y * (zv * sig));
}

// ---------------- launch ----------------
#define GEMM_SMEM (4 * STAGEF * (int)sizeof(float))   // 73728 B

static inline void roundw(const float* w, float* dst, size_t n)
{
    int n4 = (int)(n / 4);
    roundw_kernel<<<(n4 + 255) / 256, 256>>>((const float4*)w, (float4*)dst, n4);
}

extern "C" void kernel_launch(void* const* d_in, const int* in_sizes, int n_in,
                              void* d_out, int out_size)
{
    const float* hidden     = (const float*)d_in[0];
    const float* in_proj_w  = (const float*)d_in[1];
    const float* dt_proj_w  = (const float*)d_in[2];
    const float* dt_proj_b  = (const float*)d_in[3];
    const float* A_log      = (const float*)d_in[4];
    const float* D_param    = (const float*)d_in[5];
    const float* out_proj_w = (const float*)d_in[6];
    const float* gate_w     = (const float*)d_in[7];
    const float* up_w       = (const float*)d_in[8];
    const float* down_w     = (const float*)d_in[9];
    const float* norm1_w    = (const float*)d_in[10];
    const float* norm2_w    = (const float*)d_in[11];
    float* out = (float*)d_out;

    float *p_xn1, *p_zx, *p_dt, *p_ypart, *p_yg, *p_h, *p_xn2, *p_gate, *p_ff, *p_w;
    cudaGetSymbolAddress((void**)&p_xn1,  g_xn1);
    cudaGetSymbolAddress((void**)&p_zx,   g_zx);
    cudaGetSymbolAddress((void**)&p_dt,   g_dt);
    cudaGetSymbolAddress((void**)&p_ypart,g_ypart);
    cudaGetSymbolAddress((void**)&p_yg,   g_yg);
    cudaGetSymbolAddress((void**)&p_h,    g_h);
    cudaGetSymbolAddress((void**)&p_xn2,  g_xn2);
    cudaGetSymbolAddress((void**)&p_gate, g_gate);
    cudaGetSymbolAddress((void**)&p_ff,   g_ff);
    cudaGetSymbolAddress((void**)&p_w,    g_wtmp);

    cudaFuncSetAttribute(gemm128<0>, cudaFuncAttributeMaxDynamicSharedMemorySize, GEMM_SMEM);
    cudaFuncSetAttribute(gemm128<1>, cudaFuncAttributeMaxDynamicSharedMemorySize, GEMM_SMEM);
    cudaFuncSetAttribute(gemm128<2>, cudaFuncAttributeMaxDynamicSharedMemorySize, GEMM_SMEM);
    cudaFuncSetAttribute(gemm128<3>, cudaFuncAttributeMaxDynamicSharedMemorySize, GEMM_SMEM);
    cudaFuncSetAttribute(gemm128<4>, cudaFuncAttributeMaxDynamicSharedMemorySize, GEMM_SMEM);

    // 1) norm1 (tf32-RN output)
    rmsnorm_kernel<<<NTOK, 256>>>(hidden, norm1_w, p_xn1);
    // 2) in_proj (rounded weights; output rounded -> feeds dt GEMM)
    roundw(in_proj_w, p_w, (size_t)PROJ * DMODEL);
    gemm128<0><<<dim3(PROJ / 128, NTOK / 128), 256, GEMM_SMEM>>>(
        p_xn1, DMODEL, p_w, DMODEL, p_zx, PROJ, nullptr, DMODEL);
    // 3) dt = softplus(dt_raw @ dt_proj_w^T + b): K=128
    roundw(dt_proj_w, p_w, (size_t)DINNER * DTRANK);
    gemm128<1><<<dim3(DINNER / 128, NTOK / 128), 256, GEMM_SMEM>>>(
        p_zx + OFF_DT, PROJ, p_w, DTRANK, p_dt, DINNER, dt_proj_b, DTRANK);
    // 4) selective scan (partial y per warp)
    scan_kernel<<<128, 128>>>(p_zx, p_dt, A_log, p_ypart);
    // 5) combine partials + D skip + silu(z) gate (tf32-RN output -> feeds out_proj)
    combine_kernel<<<(NTOK * DINNER) / 256, 256>>>(p_ypart, p_zx, D_param, p_yg);
    // 6) out_proj + residual(hidden) -> h (full precision)
    roundw(out_proj_w, p_w, (size_t)DMODEL * DINNER);
    gemm128<2><<<dim3(DMODEL / 128, NTOK / 128), 256, GEMM_SMEM>>>(
        p_yg, DINNER, p_w, DINNER, p_h, DMODEL, hidden, DINNER);
    // 7) norm2 (tf32-RN output)
    rmsnorm_kernel<<<NTOK, 256>>>(p_h, norm2_w, p_xn2);
    // 8) gate GEMM -> g_gate (plain, full precision; consumed by silu only)
    roundw(gate_w, p_w, (size_t)DFF * DMODEL);
    gemm128<3><<<dim3(DFF / 128, NTOK / 128), 256, GEMM_SMEM>>>(
        p_xn2, DMODEL, p_w, DMODEL, p_gate, DFF, nullptr, DMODEL);
    // 9) up GEMM fused with silu(gate)*up -> g_ff (rounded -> feeds down GEMM)
    roundw(up_w, p_w, (size_t)DFF * DMODEL);
    gemm128<4><<<dim3(DFF / 128, NTOK / 128), 256, GEMM_SMEM>>>(
        p_xn2, DMODEL, p_w, DMODEL, p_ff, DFF, p_gate, DMODEL);
    // 10) down + residual(h) -> out
    roundw(down_w, p_w, (size_t)DMODEL * DFF);
    gemm128<2><<<dim3(DMODEL / 128, NTOK / 128), 256, GEMM_SMEM>>>(
        p_ff, DFF, p_w, DFF, out, DMODEL, p_h, DFF);
}

// round 11
// speedup vs baseline: 1.8804x; 1.8804x over previous
#include <cuda_runtime.h>
#include <cuda_fp16.h>
#include <cuda_bf16.h>
#include <mma.h>
#include <cstdint>

using namespace nvcuda;

#define FULLMASK 0xffffffffu

// ---------------- problem dims ----------------
#define DMODEL 2048
#define DINNER 2048
#define DXB    512
#define DSTATE 32
#define DTRANK 128
#define DFF    5632
#define NTOK   2048      // BATCH * SEQ
#define SEQLEN 1024
#define PROJ   5248      // 2*DINNER + 2*DXB + DTRANK

// column offsets inside zxbcdt
#define OFF_Z  0
#define OFF_X  2048
#define OFF_B  2560
#define OFF_C  3072
#define OFF_DT 5120

// ---------------- scratch (device globals; no allocation allowed) ----------------
__device__ float  g_xn1[(size_t)NTOK * DMODEL];
__device__ float  g_zx [(size_t)NTOK * PROJ];
__device__ float  g_dt [(size_t)NTOK * DINNER];
__device__ float  g_ypart[(size_t)128 * 1024 * 128];   // [seq][t][warp*32+p]
__device__ float  g_h  [(size_t)NTOK * DMODEL];
__device__ float  g_gate[(size_t)NTOK * DFF];
__device__ float  g_wtmp[(size_t)PROJ * DMODEL];       // tf32-rounded weight staging
__device__ __half g_ygh [(size_t)NTOK * DINNER];
__device__ __half g_xn2h[(size_t)NTOK * DMODEL];
__device__ __half g_ffh [(size_t)NTOK * DFF];
__device__ __half g_wh  [(size_t)DFF * DMODEL];        // fp16 weight staging (largest)

// ---------------- helpers ----------------
__device__ __forceinline__ float softplusf(float x) {
    return (x > 15.f) ? x : log1pf(__expf(x));
}
__device__ __forceinline__ float siluf(float x) {
    return x / (1.f + __expf(-x));
}
__device__ __forceinline__ float round_tf32(float x) {
    unsigned r;
    asm("cvt.rna.tf32.f32 %0, %1;" : "=r"(r) : "f"(x));
    return __uint_as_float(r);
}

__device__ __forceinline__ void cp_async16(void* smem_ptr, const void* gmem_ptr) {
    unsigned saddr = (unsigned)__cvta_generic_to_shared(smem_ptr);
    asm volatile("cp.async.cg.shared.global [%0], [%1], 16;\n" :: "r"(saddr), "l"(gmem_ptr));
}
#define CP_COMMIT()  asm volatile("cp.async.commit_group;\n" ::: "memory")
#define CP_WAIT0()   asm volatile("cp.async.wait_group 0;\n" ::: "memory")
#define CP_WAIT1()   asm volatile("cp.async.wait_group 1;\n" ::: "memory")

// ---------------- weight staging kernels ----------------
__global__ void roundw_kernel(const float4* __restrict__ in, float4* __restrict__ out, int n4)
{
    int i = blockIdx.x * 256 + threadIdx.x;
    if (i < n4) {
        float4 v = in[i];
        v.x = round_tf32(v.x); v.y = round_tf32(v.y);
        v.z = round_tf32(v.z); v.w = round_tf32(v.w);
        out[i] = v;
    }
}
__global__ void halfw_kernel(const float4* __restrict__ in, __half2* __restrict__ out, int n4)
{
    int i = blockIdx.x * 256 + threadIdx.x;
    if (i < n4) {
        float4 v = in[i];
        out[2 * i]     = __floats2half2_rn(v.x, v.y);
        out[2 * i + 1] = __floats2half2_rn(v.z, v.w);
    }
}

// ---------------- RMSNorm: OutT float (tf32-RN) or __half ----------------
template <typename OutT>
__global__ void rmsnorm_kernel(const float* __restrict__ x,
                               const float* __restrict__ w,
                               OutT* __restrict__ out)
{
    int t = blockIdx.x;
    const float* xr = x + (size_t)t * DMODEL;
    float s = 0.f;
    const float4* x4 = (const float4*)xr;
    #pragma unroll
    for (int i = threadIdx.x; i < DMODEL / 4; i += 256) {
        float4 v = x4[i];
        s += v.x * v.x + v.y * v.y + v.z * v.z + v.w * v.w;
    }
    #pragma unroll
    for (int o = 16; o; o >>= 1) s += __shfl_xor_sync(FULLMASK, s, o);
    __shared__ float red[8];
    if ((threadIdx.x & 31) == 0) red[threadIdx.x >> 5] = s;
    __syncthreads();
    if (threadIdx.x == 0) {
        float r = 0.f;
        #pragma unroll
        for (int i = 0; i < 8; i++) r += red[i];
        red[0] = rsqrtf(r / (float)DMODEL + 1e-5f);
    }
    __syncthreads();
    float inv = red[0];
    OutT* orow = out + (size_t)t * DMODEL;
    for (int i = threadIdx.x; i < DMODEL; i += 256) {
        float v = xr[i] * inv * w[i];
        if (sizeof(OutT) == 4) orow[i] = (OutT)round_tf32(v);
        else                   orow[i] = (OutT)__float2half(v);
    }
}

// ================= GEMM (TF32): C[M,N] = A[M,K]*B[N,K]^T =================
// Operands pre-rounded to tf32; 128x128 tile, BK=32, 256 thr, 2-stage cp.async.
// MODE 0: round_tf32(acc) (in_proj); MODE 1: softplus(acc + bias[n]) (dt)
#define SASTRIDE 36
#define STAGEF   (128 * SASTRIDE)
#define GEMM_SMEM32 (4 * STAGEF * (int)sizeof(float))   // 73728 B

template <int MODE>
__global__ __launch_bounds__(256)
void gemm32(const float* __restrict__ A, int lda,
            const float* __restrict__ B, int ldb,
            float* __restrict__ C, int ldc,
            const float* __restrict__ extra,
            int K)
{
    extern __shared__ float smem[];
    float* sA[2] = { smem,             smem + STAGEF };
    float* sB[2] = { smem + 2*STAGEF,  smem + 3*STAGEF };

    const int bm = blockIdx.y * 128;
    const int bn = blockIdx.x * 128;
    const int tid = threadIdx.x;
    const int wid = tid >> 5;
    const int wm = (wid >> 2) * 64;
    const int wn = (wid & 3) * 32;

    wmma::fragment<wmma::accumulator, 16, 16, 8, float> acc[4][2];
    #pragma unroll
    for (int i = 0; i < 4; i++)
        #pragma unroll
        for (int j = 0; j < 2; j++)
            wmma::fill_fragment(acc[i][j], 0.f);

    const int kTiles = K >> 5;

    auto load_stage = [&](int st, int k0) {
        #pragma unroll
        for (int i = 0; i < 4; i++) {
            int chunk = tid + i * 256;
            int r = chunk >> 3, c = (chunk & 7) << 2;
            cp_async16(sA[st] + r * SASTRIDE + c,
                       A + (size_t)(bm + r) * lda + k0 + c);
            cp_async16(sB[st] + r * SASTRIDE + c,
                       B + (size_t)(bn + r) * ldb + k0 + c);
        }
    };

    load_stage(0, 0);
    CP_COMMIT();

    for (int kt = 0; kt < kTiles; kt++) {
        int st = kt & 1;
        if (kt + 1 < kTiles) {
            load_stage(st ^ 1, (kt + 1) << 5);
            CP_COMMIT();
            CP_WAIT1();
        } else {
            CP_WAIT0();
        }
        __syncthreads();

        #pragma unroll
        for (int kk = 0; kk < 32; kk += 8) {
            wmma::fragment<wmma::matrix_a, 16, 16, 8, wmma::precision::tf32, wmma::row_major> af[4];
            wmma::fragment<wmma::matrix_b, 16, 16, 8, wmma::precision::tf32, wmma::col_major> bf[2];
            #pragma unroll
            for (int i = 0; i < 4; i++)
                wmma::load_matrix_sync(af[i], sA[st] + (wm + i * 16) * SASTRIDE + kk, SASTRIDE);
            #pragma unroll
            for (int j = 0; j < 2; j++)
                wmma::load_matrix_sync(bf[j], sB[st] + (wn + j * 16) * SASTRIDE + kk, SASTRIDE);
            #pragma unroll
            for (int i = 0; i < 4; i++)
                #pragma unroll
                for (int j = 0; j < 2; j++)
                    wmma::mma_sync(acc[i][j], af[i], bf[j], acc[i][j]);
        }
        __syncthreads();
    }

    #pragma unroll
    for (int i = 0; i < 4; i++)
        #pragma unroll
        for (int j = 0; j < 2; j++)
            wmma::store_matrix_sync(smem + (wm + i * 16) * 128 + wn + j * 16,
                                    acc[i][j], 128, wmma::mem_row_major);
    __syncthreads();

    #pragma unroll 4
    for (int i = tid; i < 128 * 128; i += 256) {
        int r = i >> 7, c = i & 127;
        float v = smem[i];
        int gm = bm + r, gn = bn + c;
        if (MODE == 0) v = round_tf32(v);
        if (MODE == 1) v = softplusf(v + extra[gn]);
        C[(size_t)gm * ldc + gn] = v;
    }
}

// ================= GEMM (FP16): C[M,N] = A[M,K]*B[N,K]^T =================
// 128x128 tile, BK=64 (halves), 256 thr, 2-stage cp.async, fp32 accumulate.
// MODE 2: Cf = acc + extra[m,n]  (out_proj, down)
// MODE 3: Cf = acc               (gate)
// MODE 4: Ch = half(acc * silu(extra[m,n]))  (up fused)
#define HSTRIDE 72
#define HSTAGE  (128 * HSTRIDE)                         // halves per stage per matrix
#define GEMM_SMEM16 (4 * HSTAGE * (int)sizeof(__half))  // 73728 B

template <int MODE>
__global__ __launch_bounds__(256)
void gemm16(const __half* __restrict__ A, int lda,
            const __half* __restrict__ B, int ldb,
            float* __restrict__ Cf, __half* __restrict__ Ch, int ldc,
            const float* __restrict__ extra,
            int K)
{
    extern __shared__ __half hsmem[];
    __half* sA[2] = { hsmem,             hsmem + HSTAGE };
    __half* sB[2] = { hsmem + 2*HSTAGE,  hsmem + 3*HSTAGE };

    const int bm = blockIdx.y * 128;
    const int bn = blockIdx.x * 128;
    const int tid = threadIdx.x;
    const int wid = tid >> 5;
    const int wm = (wid >> 2) * 64;
    const int wn = (wid & 3) * 32;

    wmma::fragment<wmma::accumulator, 16, 16, 16, float> acc[4][2];
    #pragma unroll
    for (int i = 0; i < 4; i++)
        #pragma unroll
        for (int j = 0; j < 2; j++)
            wmma::fill_fragment(acc[i][j], 0.f);

    const int kTiles = K >> 6;

    // loader: 128 rows x 64 halves = 128B/row = 8 chunks of 16B; 1024 chunks/matrix
    auto load_stage = [&](int st, int k0) {
        #pragma unroll
        for (int i = 0; i < 4; i++) {
            int chunk = tid + i * 256;
            int r = chunk >> 3, c = (chunk & 7) << 3;     // c in halves
            cp_async16(sA[st] + r * HSTRIDE + c,
                       A + (size_t)(bm + r) * lda + k0 + c);
            cp_async16(sB[st] + r * HSTRIDE + c,
                       B + (size_t)(bn + r) * ldb + k0 + c);
        }
    };

    load_stage(0, 0);
    CP_COMMIT();

    for (int kt = 0; kt < kTiles; kt++) {
        int st = kt & 1;
        if (kt + 1 < kTiles) {
            load_stage(st ^ 1, (kt + 1) << 6);
            CP_COMMIT();
            CP_WAIT1();
        } else {
            CP_WAIT0();
        }
        __syncthreads();

        #pragma unroll
        for (int kk = 0; kk < 64; kk += 16) {
            wmma::fragment<wmma::matrix_a, 16, 16, 16, __half, wmma::row_major> af[4];
            wmma::fragment<wmma::matrix_b, 16, 16, 16, __half, wmma::col_major> bf[2];
            #pragma unroll
            for (int i = 0; i < 4; i++)
                wmma::load_matrix_sync(af[i], sA[st] + (wm + i * 16) * HSTRIDE + kk, HSTRIDE);
            #pragma unroll
            for (int j = 0; j < 2; j++)
                wmma::load_matrix_sync(bf[j], sB[st] + (wn + j * 16) * HSTRIDE + kk, HSTRIDE);
            #pragma unroll
            for (int i = 0; i < 4; i++)
                #pragma unroll
                for (int j = 0; j < 2; j++)
                    wmma::mma_sync(acc[i][j], af[i], bf[j], acc[i][j]);
        }
        __syncthreads();
    }

    // stage C tile through smem as float (65536 B <= 73728 B)
    float* csm = (float*)hsmem;
    #pragma unroll
    for (int i = 0; i < 4; i++)
        #pragma unroll
        for (int j = 0; j < 2; j++)
            wmma::store_matrix_sync(csm + (wm + i * 16) * 128 + wn + j * 16,
                                    acc[i][j], 128, wmma::mem_row_major);
    __syncthreads();

    #pragma unroll 4
    for (int i = tid; i < 128 * 128; i += 256) {
        int r = i >> 7, c = i & 127;
        float v = csm[i];
        int gm = bm + r, gn = bn + c;
        if (MODE == 2) Cf[(size_t)gm * ldc + gn] = v + extra[(size_t)gm * ldc + gn];
        if (MODE == 3) Cf[(size_t)gm * ldc + gn] = v;
        if (MODE == 4) Ch[(size_t)gm * ldc + gn] =
            __float2half(v * siluf(extra[(size_t)gm * ldc + gn]));
    }
}

// ---------------- selective scan ----------------
#define PF 8
__global__ __launch_bounds__(128)
void scan_kernel(const float* __restrict__ zx,
                 const float* __restrict__ dtbuf,
                 const float* __restrict__ A_log,
                 float* __restrict__ ypart)
{
    int seq = blockIdx.x;          // 0..127
    int b = seq >> 6;
    int g = seq & 63;
    int w = threadIdx.x >> 5;      // 0..3
    int p = threadIdx.x & 31;      // lane
    int gkv = g >> 2;
    int nbase = w * 8;

    float An[8];
    #pragma unroll
    for (int j = 0; j < 8; j++)
        An[j] = -__expf(A_log[(size_t)(g * 32 + p) * DSTATE + nbase + j]);

    float h[8];
    #pragma unroll
    for (int j = 0; j < 8; j++) h[j] = 0.f;

    const float* dt_base = dtbuf + (size_t)b * SEQLEN * DINNER + g * 32 + p;
    const float* x_base  = zx + (size_t)b * SEQLEN * PROJ + OFF_X + gkv * 32 + p;
    const float* B_base  = zx + (size_t)b * SEQLEN * PROJ + OFF_B + gkv * 32 + p;  // lane = n
    const float* C_base  = zx + (size_t)b * SEQLEN * PROJ + OFF_C + g * 32 + p;    // lane = n
    float* yp = ypart + ((size_t)seq * SEQLEN) * 128 + w * 32 + p;

    float pdt[PF], px[PF], pB[PF], pC[PF];
    #pragma unroll
    for (int i = 0; i < PF; i++) {
        pdt[i] = __ldg(dt_base + (size_t)i * DINNER);
        px[i]  = __ldg(x_base  + (size_t)i * PROJ);
        pB[i]  = __ldg(B_base  + (size_t)i * PROJ);
        pC[i]  = __ldg(C_base  + (size_t)i * PROJ);
    }

    #pragma unroll 8
    for (int t = 0; t < SEQLEN; t++) {
        int slot = t & (PF - 1);
        float dtv = pdt[slot], xv = px[slot], Ball = pB[slot], Call = pC[slot];
        int tn = t + PF;
        if (tn < SEQLEN) {
            pdt[slot] = __ldg(dt_base + (size_t)tn * DINNER);
            px[slot]  = __ldg(x_base  + (size_t)tn * PROJ);
            pB[slot]  = __ldg(B_base  + (size_t)tn * PROJ);
            pC[slot]  = __ldg(C_base  + (size_t)tn * PROJ);
        }
        float dtx = dtv * xv;
        float acc = 0.f;
        #pragma unroll
        for (int j = 0; j < 8; j++) {
            float Bv = __shfl_sync(FULLMASK, Ball, nbase + j);
            float Cv = __shfl_sync(FULLMASK, Call, nbase + j);
            float dA = __expf(dtv * An[j]);
            h[j] = dA * h[j] + dtx * Bv;
            acc += h[j] * Cv;
        }
        yp[(size_t)t * 128] = acc;
    }
}

// ---------------- combine partial y + skip D + silu(z) gate -> half (feeds out_proj) ----------------
__global__ void combine_kernel(const float* __restrict__ ypart,
                               const float* __restrict__ zx,
                               const float* __restrict__ Dp,
                               __half* __restrict__ out)
{
    int idx = blockIdx.x * 256 + threadIdx.x;      // 0 .. NTOK*DINNER
    int tok = idx >> 11;
    int i   = idx & 2047;
    int b = tok >> 10, t = tok & 1023;
    int g = i >> 5, p = i & 31;
    int seq = b * 64 + g;
    int gkv = g >> 2;

    const float* yp = ypart + ((size_t)seq * SEQLEN + t) * 128 + p;
    float y = yp[0] + yp[32] + yp[64] + yp[96];

    float xv = zx[(size_t)tok * PROJ + OFF_X + gkv * 32 + p];
    float zv = zx[(size_t)tok * PROJ + OFF_Z + i];
    y += xv * Dp[i];
    float sig = 1.f / (1.f + __expf(-zv));
    out[(size_t)tok * DINNER + i] = __float2half(y * (zv * sig));
}

// ---------------- launch ----------------
static inline void roundw(const float* w, float* dst, size_t n)
{
    int n4 = (int)(n / 4);
    roundw_kernel<<<(n4 + 255) / 256, 256>>>((const float4*)w, (float4*)dst, n4);
}
static inline void halfw(const float* w, __half* dst, size_t n)
{
    int n4 = (int)(n / 4);
    halfw_kernel<<<(n4 + 255) / 256, 256>>>((const float4*)w, (__half2*)dst, n4);
}

extern "C" void kernel_launch(void* const* d_in, const int* in_sizes, int n_in,
                              void* d_out, int out_size)
{
    const float* hidden     = (const float*)d_in[0];
    const float* in_proj_w  = (const float*)d_in[1];
    const float* dt_proj_w  = (const float*)d_in[2];
    const float* dt_proj_b  = (const float*)d_in[3];
    const float* A_log      = (const float*)d_in[4];
    const float* D_param    = (const float*)d_in[5];
    const float* out_proj_w = (const float*)d_in[6];
    const float* gate_w     = (const float*)d_in[7];
    const float* up_w       = (const float*)d_in[8];
    const float* down_w     = (const float*)d_in[9];
    const float* norm1_w    = (const float*)d_in[10];
    const float* norm2_w    = (const float*)d_in[11];
    float* out = (float*)d_out;

    float *p_xn1, *p_zx, *p_dt, *p_ypart, *p_h, *p_gate, *p_w;
    __half *p_ygh, *p_xn2h, *p_ffh, *p_wh;
    cudaGetSymbolAddress((void**)&p_xn1,  g_xn1);
    cudaGetSymbolAddress((void**)&p_zx,   g_zx);
    cudaGetSymbolAddress((void**)&p_dt,   g_dt);
    cudaGetSymbolAddress((void**)&p_ypart,g_ypart);
    cudaGetSymbolAddress((void**)&p_h,    g_h);
    cudaGetSymbolAddress((void**)&p_gate, g_gate);
    cudaGetSymbolAddress((void**)&p_w,    g_wtmp);
    cudaGetSymbolAddress((void**)&p_ygh,  g_ygh);
    cudaGetSymbolAddress((void**)&p_xn2h, g_xn2h);
    cudaGetSymbolAddress((void**)&p_ffh,  g_ffh);
    cudaGetSymbolAddress((void**)&p_wh,   g_wh);

    cudaFuncSetAttribute(gemm32<0>, cudaFuncAttributeMaxDynamicSharedMemorySize, GEMM_SMEM32);
    cudaFuncSetAttribute(gemm32<1>, cudaFuncAttributeMaxDynamicSharedMemorySize, GEMM_SMEM32);
    cudaFuncSetAttribute(gemm16<2>, cudaFuncAttributeMaxDynamicSharedMemorySize, GEMM_SMEM16);
    cudaFuncSetAttribute(gemm16<3>, cudaFuncAttributeMaxDynamicSharedMemorySize, GEMM_SMEM16);
    cudaFuncSetAttribute(gemm16<4>, cudaFuncAttributeMaxDynamicSharedMemorySize, GEMM_SMEM16);

    // 1) norm1 (tf32-RN fp32 output)
    rmsnorm_kernel<float><<<NTOK, 256>>>(hidden, norm1_w, p_xn1);
    // 2) in_proj (tf32): output rounded -> zx (feeds dt GEMM + scan)
    roundw(in_proj_w, p_w, (size_t)PROJ * DMODEL);
    gemm32<0><<<dim3(PROJ / 128, NTOK / 128), 256, GEMM_SMEM32>>>(
        p_xn1, DMODEL, p_w, DMODEL, p_zx, PROJ, nullptr, DMODEL);
    // 3) dt (tf32) = softplus(dt_raw @ dt_proj_w^T + b)
    roundw(dt_proj_w, p_w, (size_t)DINNER * DTRANK);
    gemm32<1><<<dim3(DINNER / 128, NTOK / 128), 256, GEMM_SMEM32>>>(
        p_zx + OFF_DT, PROJ, p_w, DTRANK, p_dt, DINNER, dt_proj_b, DTRANK);
    // 4) selective scan
    scan_kernel<<<128, 128>>>(p_zx, p_dt, A_log, p_ypart);
    // 5) combine -> ygh (fp16)
    combine_kernel<<<(NTOK * DINNER) / 256, 256>>>(p_ypart, p_zx, D_param, p_ygh);
    // 6) out_proj (fp16) + residual(hidden) -> h (fp32)
    halfw(out_proj_w, p_wh, (size_t)DMODEL * DINNER);
    gemm16<2><<<dim3(DMODEL / 128, NTOK / 128), 256, GEMM_SMEM16>>>(
        p_ygh, DINNER, p_wh, DINNER, p_h, nullptr, DMODEL, hidden, DINNER);
    // 7) norm2 -> xn2h (fp16)
    rmsnorm_kernel<__half><<<NTOK, 256>>>(p_h, norm2_w, p_xn2h);
    // 8) gate GEMM (fp16) -> g_gate (fp32)
    halfw(gate_w, p_wh, (size_t)DFF * DMODEL);
    gemm16<3><<<dim3(DFF / 128, NTOK / 128), 256, GEMM_SMEM16>>>(
        p_xn2h, DMODEL, p_wh, DMODEL, p_gate, nullptr, DFF, nullptr, DMODEL);
    // 9) up GEMM (fp16) fused silu(gate)*up -> ffh (fp16)
    halfw(up_w, p_wh, (size_t)DFF * DMODEL);
    gemm16<4><<<dim3(DFF / 128, NTOK / 128), 256, GEMM_SMEM16>>>(
        p_xn2h, DMODEL, p_wh, DMODEL, nullptr, p_ffh, DFF, p_gate, DMODEL);
    // 10) down (fp16) + residual(h) -> out (fp32)
    halfw(down_w, p_wh, (size_t)DMODEL * DFF);
    gemm16<2><<<dim3(DMODEL / 128, NTOK / 128), 256, GEMM_SMEM16>>>(
        p_ffh, DFF, p_wh, DFF, out, nullptr, DMODEL, p_h, DFF);
}